// round 4
// baseline (speedup 1.0000x reference)
#include <cuda_runtime.h>
#include <math_constants.h>

// ---------------------------------------------------------------------------
// SC_Att_Bridge: 5-level spatial attention (CBAM-style), fp32.
// Phase 1: per-pixel channel mean+max  -> g_avg/g_max (warp-owned pixels,
//          no smem, 8-deep LDG.128 batching)
// Phase 2: dilated 7x7 conv (d=3,p=9) + bias + sigmoid -> g_att
// Phase 3: out = t * (1 + att)  (float4)
// ---------------------------------------------------------------------------

#define NTOT_PIX 698368   // sum over tensors of N*H*W (N=8)

__device__ float g_avg[NTOT_PIX];
__device__ float g_max[NTOT_PIX];
__device__ float g_att[NTOT_PIX];

// shapes: (8,64,256,256)(8,128,128,128)(8,256,64,64)(8,512,32,32)(8,512,16,16)
__constant__ int c_C[5]       = {64, 128, 256, 512, 512};
__constant__ int c_HW[5]      = {65536, 16384, 4096, 1024, 256};
__constant__ int c_lgHW[5]    = {16, 14, 12, 10, 8};
__constant__ int c_W[5]       = {256, 128, 64, 32, 16};
__constant__ int c_poff[5]    = {0, 524288, 655360, 688128, 696320};          // pixel offsets
__constant__ int c_eoff[5]    = {0, 33554432, 50331648, 58720256, 62914560};  // element offsets
__constant__ int c_lgCHW[5]   = {22, 21, 20, 19, 17};
__constant__ int c_convcum[5] = {0, 2048, 2560, 2688, 2720};   // conv blocks
__constant__ int c_tpn[5]     = {256, 64, 16, 4, 1};           // 16x16 tiles per image
__constant__ int c_tilesX[5]  = {16, 8, 4, 2, 1};

// ---------------------------------------------------------------------------
// Phase 1: channel mean + max. One warp owns 128 contiguous pixels
// (32 lanes x float4) and loops over ALL C channels. No shared memory,
// no cross-thread combine. Block = 8 warps = 1024 pixels. Grid = 682.
// Inner loop batches 8 independent LDG.128 before consuming -> 8-deep MLP.
// ---------------------------------------------------------------------------
__global__ __launch_bounds__(256) void reduce_kernel(
    const float* __restrict__ t0, const float* __restrict__ t1,
    const float* __restrict__ t2, const float* __restrict__ t3,
    const float* __restrict__ t4)
{
    const int b = blockIdx.x;
    int i = 0;
    if (b >= 512) i = 1;   // 524288/1024
    if (b >= 640) i = 2;   // 655360/1024
    if (b >= 672) i = 3;   // 688128/1024
    if (b >= 680) i = 4;   // 696320/1024

    const float* srcs[5] = {t0, t1, t2, t3, t4};
    const float* __restrict__ src = srcs[i];

    const int tid  = threadIdx.x;
    const int lane = tid & 31;
    const int w    = tid >> 5;

    const int gpx   = (b << 10) + (w << 7) + (lane << 2); // global pixel (x4)
    const int local = gpx - c_poff[i];                    // pixel within tensor

    const int HW  = c_HW[i];
    const int C   = c_C[i];
    const int n   = local >> c_lgHW[i];
    const int hw  = local & (HW - 1);
    const int HW4 = HW >> 2;

    const float4* __restrict__ p =
        reinterpret_cast<const float4*>(src + (size_t)n * C * HW + hw);

    float4 s = make_float4(0.f, 0.f, 0.f, 0.f);
    float4 m = make_float4(-CUDART_INF_F, -CUDART_INF_F, -CUDART_INF_F, -CUDART_INF_F);

    for (int c = 0; c < C; c += 8) {
        float4 v[8];
#pragma unroll
        for (int k = 0; k < 8; k++)
            v[k] = __ldg(p + (size_t)(c + k) * HW4);
#pragma unroll
        for (int k = 0; k < 8; k++) {
            s.x += v[k].x; s.y += v[k].y; s.z += v[k].z; s.w += v[k].w;
            m.x = fmaxf(m.x, v[k].x); m.y = fmaxf(m.y, v[k].y);
            m.z = fmaxf(m.z, v[k].z); m.w = fmaxf(m.w, v[k].w);
        }
    }

    const float inv = 1.0f / (float)C;
    s.x *= inv; s.y *= inv; s.z *= inv; s.w *= inv;

    const int q4 = gpx >> 2;
    reinterpret_cast<float4*>(g_avg)[q4] = s;
    reinterpret_cast<float4*>(g_max)[q4] = m;
}

// ---------------------------------------------------------------------------
// Phase 2: dilated 7x7 conv (dilation 3, zero pad 9) over [avg,max], + bias,
// sigmoid. Block = 16x16 output tile; SMEM holds 34x34 halo of both maps.
// Grid = 2728. lax.conv is cross-correlation (no kernel flip).
// ---------------------------------------------------------------------------
__global__ __launch_bounds__(256) void conv_kernel(
    const float* __restrict__ cw, const float* __restrict__ cb)
{
    __shared__ float s_av[34 * 34];
    __shared__ float s_mx[34 * 34];
    __shared__ float s_w[98];

    int b = blockIdx.x;
    int i = 0;
    if (b >= 2048) i = 1;
    if (b >= 2560) i = 2;
    if (b >= 2688) i = 3;
    if (b >= 2720) i = 4;

    const int r      = b - c_convcum[i];
    const int tpn    = c_tpn[i];
    const int n      = r / tpn;
    const int tl     = r - n * tpn;
    const int tilesX = c_tilesX[i];
    const int ty0    = (tl / tilesX) << 4;
    const int tx0    = (tl % tilesX) << 4;
    const int Wd     = c_W[i];
    const int po     = c_poff[i] + (n << c_lgHW[i]);

    const int tid = threadIdx.x;
    if (tid < 98) s_w[tid] = cw[tid];

    for (int idx = tid; idx < 34 * 34; idx += 256) {
        int yy = idx / 34;
        int xx = idx - yy * 34;
        int h  = ty0 + yy - 9;
        int w  = tx0 + xx - 9;
        float a = 0.0f, m = 0.0f;
        if ((unsigned)h < (unsigned)Wd && (unsigned)w < (unsigned)Wd) { // H==W
            int q = po + h * Wd + w;
            a = g_avg[q];
            m = g_max[q];
        }
        s_av[idx] = a;
        s_mx[idx] = m;
    }
    __syncthreads();

    const int ty = tid >> 4;
    const int tx = tid & 15;

    float acc = cb[0];
#pragma unroll
    for (int kh = 0; kh < 7; kh++) {
#pragma unroll
        for (int kw = 0; kw < 7; kw++) {
            int s = (ty + kh * 3) * 34 + (tx + kw * 3);
            acc = fmaf(s_av[s], s_w[kh * 7 + kw],      acc);
            acc = fmaf(s_mx[s], s_w[49 + kh * 7 + kw], acc);
        }
    }
    float att = 1.0f / (1.0f + expf(-acc));
    g_att[po + (ty0 + ty) * Wd + (tx0 + tx)] = att;
}

// ---------------------------------------------------------------------------
// Phase 3: out = t * (1 + att). float4 everywhere; att map is L2-resident.
// Grid = 62464 blocks exactly (R2 form — best measured).
// ---------------------------------------------------------------------------
__global__ __launch_bounds__(256) void gate_kernel(
    const float* __restrict__ t0, const float* __restrict__ t1,
    const float* __restrict__ t2, const float* __restrict__ t3,
    const float* __restrict__ t4, float* __restrict__ out)
{
    const int gid = blockIdx.x * 256 + threadIdx.x;
    const int e   = gid << 2;   // element index, < 63,963,136 (fits int32)

    int i = 0;
    if (e >= 33554432) i = 1;
    if (e >= 50331648) i = 2;
    if (e >= 58720256) i = 3;
    if (e >= 62914560) i = 4;

    const float* srcs[5] = {t0, t1, t2, t3, t4};
    const float* __restrict__ src = srcs[i];

    const int local = e - c_eoff[i];
    const int n     = local >> c_lgCHW[i];
    const int hw    = local & (c_HW[i] - 1);
    const int p     = c_poff[i] + (n << c_lgHW[i]) + hw;  // %4 == 0

    const float4 a = *reinterpret_cast<const float4*>(&g_att[p]);
    const float4 v = *reinterpret_cast<const float4*>(&src[local]);

    float4 o;
    o.x = fmaf(v.x, a.x, v.x);
    o.y = fmaf(v.y, a.y, v.y);
    o.z = fmaf(v.z, a.z, v.z);
    o.w = fmaf(v.w, a.w, v.w);

    reinterpret_cast<float4*>(out)[gid] = o;
}

// ---------------------------------------------------------------------------
extern "C" void kernel_launch(void* const* d_in, const int* in_sizes, int n_in,
                              void* d_out, int out_size)
{
    const float* t0 = (const float*)d_in[0];
    const float* t1 = (const float*)d_in[1];
    const float* t2 = (const float*)d_in[2];
    const float* t3 = (const float*)d_in[3];
    const float* t4 = (const float*)d_in[4];
    const float* cw = (const float*)d_in[5];
    const float* cb = (const float*)d_in[6];
    float* out = (float*)d_out;

    reduce_kernel<<<682, 256>>>(t0, t1, t2, t3, t4);
    conv_kernel<<<2728, 256>>>(cw, cb);
    gate_kernel<<<62464, 256>>>(t0, t1, t2, t3, t4, out);
}

// round 6
// speedup vs baseline: 1.7988x; 1.7988x over previous
#include <cuda_runtime.h>
#include <math_constants.h>

// ---------------------------------------------------------------------------
// SC_Att_Bridge: 5-level spatial attention (CBAM-style), fp32.
// Phase 1: per-pixel channel mean+max -> g_avg/g_max (R2 form: best measured)
// Phase 2: dilated 7x7 conv (d=3,p=9) + bias + sigmoid -> g_att
// Phase 3: out = t*(1+att), tiled: att chunk in SMEM reused across channels
// ---------------------------------------------------------------------------

#define NTOT_PIX 698368   // sum over tensors of N*H*W (N=8)

__device__ float g_avg[NTOT_PIX];
__device__ float g_max[NTOT_PIX];
__device__ float g_att[NTOT_PIX];

// shapes: (8,64,256,256)(8,128,128,128)(8,256,64,64)(8,512,32,32)(8,512,16,16)
__constant__ int c_C[5]       = {64, 128, 256, 512, 512};
__constant__ int c_HW[5]      = {65536, 16384, 4096, 1024, 256};
__constant__ int c_lgHW[5]    = {16, 14, 12, 10, 8};
__constant__ int c_W[5]       = {256, 128, 64, 32, 16};
__constant__ int c_poff[5]    = {0, 524288, 655360, 688128, 696320};          // pixel offsets
__constant__ int c_eoff[5]    = {0, 33554432, 50331648, 58720256, 62914560};  // element offsets
__constant__ int c_redcum[5]  = {0, 4096, 5120, 5376, 5440};   // reduce blocks (128 px each)
__constant__ int c_convcum[5] = {0, 2048, 2560, 2688, 2720};   // conv blocks
__constant__ int c_tpn[5]     = {256, 64, 16, 4, 1};           // 16x16 tiles per image
__constant__ int c_tilesX[5]  = {16, 8, 4, 2, 1};

// gate tiling: 8192 elements/block = chunkpx pixels x nch channels
// per-tensor blocks: 4096,2048,1024,512,128 -> total 7808
__constant__ int c_gcum[5]    = {0, 4096, 6144, 7168, 7680};   // gate block offsets
__constant__ int c_lgpnb[5]   = {9, 8, 7, 6, 4};               // lg(blocks per image n)
__constant__ int c_lgnhw[5]   = {6, 4, 2, 0, 0};               // lg(hw-chunks per image)
__constant__ int c_lgnch[5]   = {3, 3, 3, 3, 5};               // lg(channels per block)
__constant__ int c_lgchunk[5] = {10, 10, 10, 10, 8};           // lg(pixels per chunk)

// ---------------------------------------------------------------------------
// Phase 1: channel mean + max, float4-vectorized (R2 form).
// Block = 256 threads = 32 lanes x 8 channel-groups; each lane owns 4
// contiguous pixels (float4). Block covers 128 pixels. Grid = 5456.
// ---------------------------------------------------------------------------
__global__ __launch_bounds__(256) void reduce_kernel(
    const float* __restrict__ t0, const float* __restrict__ t1,
    const float* __restrict__ t2, const float* __restrict__ t3,
    const float* __restrict__ t4)
{
    __shared__ float4 ss[256];
    __shared__ float4 sm[256];

    int b = blockIdx.x;
    int i = 0;
    if (b >= 4096) i = 1;
    if (b >= 5120) i = 2;
    if (b >= 5376) i = 3;
    if (b >= 5440) i = 4;

    const float* srcs[5] = {t0, t1, t2, t3, t4};
    const float* __restrict__ src = srcs[i];

    const int tid   = threadIdx.x;
    const int lane  = tid & 31;
    const int grp   = tid >> 5;
    const int base  = (b - c_redcum[i]) << 7;      // 128 pixels per block
    const int pixel = base + (lane << 2);          // first of 4 contiguous pixels

    const int HW   = c_HW[i];
    const int C    = c_C[i];
    const int n    = pixel >> c_lgHW[i];
    const int hw   = pixel & (HW - 1);             // multiple of 4; no HW-crossing
    const int HW4  = HW >> 2;

    const float4* __restrict__ p =
        reinterpret_cast<const float4*>(src + (size_t)n * C * HW + hw);

    float4 s = make_float4(0.f, 0.f, 0.f, 0.f);
    float4 m = make_float4(-CUDART_INF_F, -CUDART_INF_F, -CUDART_INF_F, -CUDART_INF_F);
#pragma unroll 4
    for (int c = grp; c < C; c += 8) {
        float4 v = __ldg(p + (size_t)c * HW4);
        s.x += v.x; s.y += v.y; s.z += v.z; s.w += v.w;
        m.x = fmaxf(m.x, v.x); m.y = fmaxf(m.y, v.y);
        m.z = fmaxf(m.z, v.z); m.w = fmaxf(m.w, v.w);
    }
    ss[tid] = s;
    sm[tid] = m;
    __syncthreads();

    if (tid < 32) {
#pragma unroll
        for (int g = 1; g < 8; g++) {
            float4 s2 = ss[g * 32 + tid];
            float4 m2 = sm[g * 32 + tid];
            s.x += s2.x; s.y += s2.y; s.z += s2.z; s.w += s2.w;
            m.x = fmaxf(m.x, m2.x); m.y = fmaxf(m.y, m2.y);
            m.z = fmaxf(m.z, m2.z); m.w = fmaxf(m.w, m2.w);
        }
        const float inv = 1.0f / (float)C;
        s.x *= inv; s.y *= inv; s.z *= inv; s.w *= inv;
        const int q4 = (c_poff[i] + pixel) >> 2;
        reinterpret_cast<float4*>(g_avg)[q4] = s;
        reinterpret_cast<float4*>(g_max)[q4] = m;
    }
}

// ---------------------------------------------------------------------------
// Phase 2: dilated 7x7 conv (dilation 3, zero pad 9) over [avg,max], + bias,
// sigmoid. Block = 16x16 output tile; SMEM holds 34x34 halo of both maps.
// Grid = 2728. lax.conv is cross-correlation (no kernel flip).
// ---------------------------------------------------------------------------
__global__ __launch_bounds__(256) void conv_kernel(
    const float* __restrict__ cw, const float* __restrict__ cb)
{
    __shared__ float s_av[34 * 34];
    __shared__ float s_mx[34 * 34];
    __shared__ float s_w[98];

    int b = blockIdx.x;
    int i = 0;
    if (b >= 2048) i = 1;
    if (b >= 2560) i = 2;
    if (b >= 2688) i = 3;
    if (b >= 2720) i = 4;

    const int r      = b - c_convcum[i];
    const int tpn    = c_tpn[i];
    const int n      = r / tpn;
    const int tl     = r - n * tpn;
    const int tilesX = c_tilesX[i];
    const int ty0    = (tl / tilesX) << 4;
    const int tx0    = (tl % tilesX) << 4;
    const int Wd     = c_W[i];
    const int po     = c_poff[i] + (n << c_lgHW[i]);

    const int tid = threadIdx.x;
    if (tid < 98) s_w[tid] = cw[tid];

    for (int idx = tid; idx < 34 * 34; idx += 256) {
        int yy = idx / 34;
        int xx = idx - yy * 34;
        int h  = ty0 + yy - 9;
        int w  = tx0 + xx - 9;
        float a = 0.0f, m = 0.0f;
        if ((unsigned)h < (unsigned)Wd && (unsigned)w < (unsigned)Wd) { // H==W
            int q = po + h * Wd + w;
            a = g_avg[q];
            m = g_max[q];
        }
        s_av[idx] = a;
        s_mx[idx] = m;
    }
    __syncthreads();

    const int ty = tid >> 4;
    const int tx = tid & 15;

    float acc = cb[0];
#pragma unroll
    for (int kh = 0; kh < 7; kh++) {
#pragma unroll
        for (int kw = 0; kw < 7; kw++) {
            int s = (ty + kh * 3) * 34 + (tx + kw * 3);
            acc = fmaf(s_av[s], s_w[kh * 7 + kw],      acc);
            acc = fmaf(s_mx[s], s_w[49 + kh * 7 + kw], acc);
        }
    }
    float att = 1.0f / (1.0f + expf(-acc));
    g_att[po + (ty0 + ty) * Wd + (tx0 + tx)] = att;
}

// ---------------------------------------------------------------------------
// Phase 3: out = t * (1 + att), tiled for att reuse.
// Block = 256 threads handles one tile of 8192 elements:
//   chunkpx pixels (1024, or 256 for t5) x nch channels (8, or 32 for t5).
// att for the pixel chunk is staged in SMEM once and reused nch times.
// Each thread processes 8 float4s with batched loads (8-deep MLP).
// Grid = 7808 blocks, perfectly uniform work.
// ---------------------------------------------------------------------------
__global__ __launch_bounds__(256) void gate_kernel(
    const float* __restrict__ t0, const float* __restrict__ t1,
    const float* __restrict__ t2, const float* __restrict__ t3,
    const float* __restrict__ t4, float* __restrict__ out)
{
    __shared__ float s_att[1024];

    const int b = blockIdx.x;
    int i = 0;
    if (b >= 4096) i = 1;
    if (b >= 6144) i = 2;
    if (b >= 7168) i = 3;
    if (b >= 7680) i = 4;

    const float* srcs[5] = {t0, t1, t2, t3, t4};
    const float* __restrict__ src = srcs[i];

    const int tid     = threadIdx.x;
    const int r       = b - c_gcum[i];
    const int lgpnb   = c_lgpnb[i];
    const int lgnhw   = c_lgnhw[i];
    const int lgnch   = c_lgnch[i];
    const int lgchunk = c_lgchunk[i];
    const int lgHW    = c_lgHW[i];

    const int n      = r >> lgpnb;
    const int rem    = r & ((1 << lgpnb) - 1);
    const int cchunk = rem >> lgnhw;
    const int hwc    = rem & ((1 << lgnhw) - 1);
    const int c0     = cchunk << lgnch;
    const int hw0    = hwc << lgchunk;
    const int chunkpx = 1 << lgchunk;

    // element base within tensor and att base pixel (both float4-aligned)
    const int ebase   = ((n * c_C[i] + c0) << lgHW) + hw0;
    const int attbase = c_poff[i] + (n << lgHW) + hw0;

    // stage att chunk into SMEM (chunkpx/4 float4 loads)
    if (tid < (chunkpx >> 2)) {
        reinterpret_cast<float4*>(s_att)[tid] =
            *reinterpret_cast<const float4*>(&g_att[attbase + (tid << 2)]);
    }
    __syncthreads();

    // 8 float4s per thread over the 8192-element tile; flat index
    // f = (j*256 + tid)*4 -> channel = f >> lgchunk, pixel = f & (chunkpx-1)
    const int chunkm1 = chunkpx - 1;

    float4 v[8];
    int addr[8];
#pragma unroll
    for (int j = 0; j < 8; j++) {
        int f  = ((j << 8) + tid) << 2;
        int ch = f >> lgchunk;
        int px = f & chunkm1;
        addr[j] = ebase + (ch << lgHW) + px;
        v[j] = *reinterpret_cast<const float4*>(&src[addr[j]]);
    }
    const int eoff = c_eoff[i];
#pragma unroll
    for (int j = 0; j < 8; j++) {
        int f  = ((j << 8) + tid) << 2;
        int px = f & chunkm1;
        float4 a = *reinterpret_cast<const float4*>(&s_att[px]);
        float4 o;
        o.x = fmaf(v[j].x, a.x, v[j].x);
        o.y = fmaf(v[j].y, a.y, v[j].y);
        o.z = fmaf(v[j].z, a.z, v[j].z);
        o.w = fmaf(v[j].w, a.w, v[j].w);
        *reinterpret_cast<float4*>(&out[eoff + addr[j]]) = o;
    }
}

// ---------------------------------------------------------------------------
extern "C" void kernel_launch(void* const* d_in, const int* in_sizes, int n_in,
                              void* d_out, int out_size)
{
    const float* t0 = (const float*)d_in[0];
    const float* t1 = (const float*)d_in[1];
    const float* t2 = (const float*)d_in[2];
    const float* t3 = (const float*)d_in[3];
    const float* t4 = (const float*)d_in[4];
    const float* cw = (const float*)d_in[5];
    const float* cb = (const float*)d_in[6];
    float* out = (float*)d_out;

    reduce_kernel<<<5456, 256>>>(t0, t1, t2, t3, t4);
    conv_kernel<<<2728, 256>>>(cw, cb);
    gate_kernel<<<7808, 256>>>(t0, t1, t2, t3, t4, out);
}